// round 14
// baseline (speedup 1.0000x reference)
#include <cuda_runtime.h>
#include <cuda_fp16.h>
#include <cstdint>
#include <math.h>

// Problem constants
#define VV 27
#define EE 64
#define HH 128
#define BB 256
#define SE 512
#define SD 512

typedef unsigned long long ull;
typedef unsigned int u32;

// Scratch for decoder hidden states, fp16: [B, S_DEC, H] = 32 MB.
__device__ __half g_dec_h[(size_t)BB * SD * HH];

// ---- packed fp32x2 helpers (sm_103a FFMA2 / FADD2) ----
__device__ __forceinline__ void ffma2(ull& d, ull a, ull b) {
    asm("fma.rn.f32x2 %0, %1, %2, %0;" : "+l"(d) : "l"(a), "l"(b));
}
__device__ __forceinline__ ull addp2(ull a, ull b) {
    ull r; asm("add.rn.f32x2 %0, %1, %2;" : "=l"(r) : "l"(a), "l"(b)); return r;
}
__device__ __forceinline__ ull pack2(float x, float y) {
    ull r; asm("mov.b64 %0, {%1, %2};" : "=l"(r) : "f"(x), "f"(y)); return r;
}
__device__ __forceinline__ float2 unpack2(ull v) {
    float2 r; asm("mov.b64 {%0, %1}, %2;" : "=f"(r.x), "=f"(r.y) : "l"(v)); return r;
}

// Fast-but-accurate tanh: 1 - 2/(exp(2x)+1). abs err ~1e-6.
__device__ __forceinline__ float fast_tanh(float x) {
    float e = __expf(x * 2.0f);
    return 1.0f - __fdividef(2.0f, e + 1.0f);
}

// =====================================================================
// Kernel 1: fused encoder+decoder scan, R12 ring + LOAD-pinned early
// arrive. 128 CTAs x 256 threads; grp = tid>>7 = row, j = tid&127.
// Ring model (measured): P = 2*(A + 47), where A = time from release
// to the arrive-pin being ready. R12 pinned the arrive on the finished
// dot (A~236 -> P~570). Here the arrive is pinned on a LOADED h value
// (ready ~90 cyc after release): the partner is released while this
// group's FFMA2s still issue, so the shared FFMA2 pipe floor (384/step)
// bounds the period instead of the latency ring. The arrive carries a
// register dependence only, placed between the load batch and the FFMA
// block -> ptxas LDS front-batching preserved (the R11 failure mode).
// Memory safety: groups share no hbuf; each group's own bar.sync still
// orders its STS(t-1) before its LDS(t). Token counts identical to R12.
// =====================================================================
__global__ void __launch_bounds__(256, 1) scan_kernel(
    const int*   __restrict__ enc_ids, const int* __restrict__ dec_ids,
    const float* __restrict__ embed,
    const float* __restrict__ enc_Wx, const float* __restrict__ enc_Wh,
    const float* __restrict__ enc_b,
    const float* __restrict__ dec_Wx, const float* __restrict__ dec_Wh,
    const float* __restrict__ dec_b)
{
    __shared__ float tabE[VV][HH];
    __shared__ float tabD[VV][HH];
    __shared__ float emb_s[VV * EE];
    __shared__ __align__(16) float hbuf[2][2][HH];
    __shared__ int   idsE[2][SE];
    __shared__ int   idsD[2][SD];

    const int tid  = threadIdx.x;
    const int grp  = tid >> 7;
    const int j    = tid & (HH - 1);
    const int row0 = blockIdx.x * 2;
    const int row  = row0 + grp;

    for (int i = tid; i < VV * EE; i += 256) emb_s[i] = embed[i];
    for (int i = tid; i < SE; i += 256) {
        idsE[0][i] = enc_ids[(size_t)row0 * SE + i];
        idsE[1][i] = enc_ids[(size_t)(row0 + 1) * SE + i];
    }
    for (int i = tid; i < SD; i += 256) {
        idsD[0][i] = dec_ids[(size_t)row0 * SD + i];
        idsD[1][i] = dec_ids[(size_t)(row0 + 1) * SD + i];
    }
    __syncthreads();

    for (int idx = tid; idx < VV * HH; idx += 256) {
        const int v = idx / HH;
        const int h = idx - v * HH;
        float sE = enc_b[h];
        float sD = dec_b[h];
        #pragma unroll 8
        for (int e = 0; e < EE; e++) {
            const float em = emb_s[v * EE + e];
            sE = fmaf(em, enc_Wx[e * HH + h], sE);
            sD = fmaf(em, dec_Wx[e * HH + h], sD);
        }
        tabE[v][h] = sE;
        tabD[v][h] = sD;
    }

    if (grp == 0) { hbuf[0][0][j] = 0.0f; hbuf[0][1][j] = 0.0f; }
    __syncthreads();

    ull w2[HH / 2];
    #pragma unroll
    for (int k = 0; k < HH / 2; k++)
        w2[k] = pack2(enc_Wh[(2 * k) * HH + j], enc_Wh[(2 * k + 1) * HH + j]);

    // prime the ring
    if (grp == 1)
        asm volatile("bar.arrive 4, 256;" ::: "memory");

    // ---- encoder phase ----
    int cur = 0;
    float tb = tabE[idsE[grp][0]][j];
    for (int t = 0; t < SE; t++) {
        if (grp == 0) asm volatile("bar.sync 4, 256;" ::: "memory");
        else          asm volatile("bar.sync 3, 256;" ::: "memory");

        const ulonglong2* hq = (const ulonglong2*)hbuf[cur][grp];
        // load one h chunk explicitly; the EARLY arrive pins on its data
        const ulonglong2 hL = hq[31];
        if (grp == 0) asm volatile("bar.arrive 3, 256;" :: "l"(hL.x));
        else          asm volatile("bar.arrive 4, 256;" :: "l"(hL.x));

        ull a0 = pack2(tb, 0.0f), a1 = 0, a2 = 0, a3 = 0;
        #pragma unroll
        for (int q = 0; q < 30; q += 2) {           // hq[0..29]
            ulonglong2 h0 = hq[q];
            ulonglong2 h1 = hq[q + 1];
            ffma2(a0, h0.x, w2[2 * q + 0]);
            ffma2(a1, h0.y, w2[2 * q + 1]);
            ffma2(a2, h1.x, w2[2 * q + 2]);
            ffma2(a3, h1.y, w2[2 * q + 3]);
        }
        {                                            // hq[30] + hL(=hq[31])
            ulonglong2 h0 = hq[30];
            ffma2(a0, h0.x, w2[60]);
            ffma2(a1, h0.y, w2[61]);
            ffma2(a2, hL.x, w2[62]);
            ffma2(a3, hL.y, w2[63]);
        }

        const int tn = (t + 1 < SE) ? t + 1 : t;
        const float nb = tabE[idsE[grp][tn]][j];

        float2 s = unpack2(addp2(addp2(a0, a2), addp2(a1, a3)));
        const float hn = fast_tanh(s.x + s.y);
        hbuf[cur ^ 1][grp][j] = hn;
        cur ^= 1;
        tb = nb;
    }

    // ---- decoder phase ----
    #pragma unroll
    for (int k = 0; k < HH / 2; k++)
        w2[k] = pack2(dec_Wh[(2 * k) * HH + j], dec_Wh[(2 * k + 1) * HH + j]);

    __half* outrow = g_dec_h + (size_t)row * SD * HH;
    tb = tabD[idsD[grp][0]][j];
    for (int t = 0; t < SD; t++) {
        if (grp == 0) asm volatile("bar.sync 4, 256;" ::: "memory");
        else          asm volatile("bar.sync 3, 256;" ::: "memory");

        const ulonglong2* hq = (const ulonglong2*)hbuf[cur][grp];
        const ulonglong2 hL = hq[31];
        if (grp == 0) asm volatile("bar.arrive 3, 256;" :: "l"(hL.x));
        else          asm volatile("bar.arrive 4, 256;" :: "l"(hL.x));

        ull a0 = pack2(tb, 0.0f), a1 = 0, a2 = 0, a3 = 0;
        #pragma unroll
        for (int q = 0; q < 30; q += 2) {
            ulonglong2 h0 = hq[q];
            ulonglong2 h1 = hq[q + 1];
            ffma2(a0, h0.x, w2[2 * q + 0]);
            ffma2(a1, h0.y, w2[2 * q + 1]);
            ffma2(a2, h1.x, w2[2 * q + 2]);
            ffma2(a3, h1.y, w2[2 * q + 3]);
        }
        {
            ulonglong2 h0 = hq[30];
            ffma2(a0, h0.x, w2[60]);
            ffma2(a1, h0.y, w2[61]);
            ffma2(a2, hL.x, w2[62]);
            ffma2(a3, hL.y, w2[63]);
        }

        const int tn = (t + 1 < SD) ? t + 1 : t;
        const float nb = tabD[idsD[grp][tn]][j];

        float2 s = unpack2(addp2(addp2(a0, a2), addp2(a1, a3)));
        const float hn = fast_tanh(s.x + s.y);
        hbuf[cur ^ 1][grp][j] = hn;
        outrow[t * HH + j] = __float2half_rn(hn);   // off-chain store
        cur ^= 1;
        tb = nb;
    }
}

// =====================================================================
// Kernel 2: logits via tensor cores (64-token tiles, 2048 CTAs x 128
// threads). Logit tile Ls ALIASES the dead h tile (lifetimes separated
// by __syncthreads) -> smem 33KB -> 26KB; launch_bounds(128,7) lifts
// occupancy. Coalesced float4 epilogue.
// =====================================================================
__global__ void __launch_bounds__(128, 7) logits_kernel(
    const float* __restrict__ dense_W, const float* __restrict__ dense_b,
    float* __restrict__ out)
{
    __shared__ __align__(16) __half hs[64 * 136];    // 17 KB h tile
    __shared__ __align__(16) __half w_s[32 * 136];   // 8.5 KB W^T
    __shared__ float bias_s[32];
    float* Ls = (float*)hs;   // 64*27*4 = 6.9 KB, aliases dead hs

    const int tid  = threadIdx.x;
    const int lane = tid & 31;
    const int wid  = tid >> 5;            // 0..3
    const size_t tok0 = (size_t)blockIdx.x * 64;

    const uint4* src = (const uint4*)(g_dec_h + tok0 * HH);
    #pragma unroll
    for (int i = 0; i < 8; i++) {
        const int idx = tid + 128 * i;
        const int row = idx >> 4, part = idx & 15;
        *(uint4*)&hs[row * 136 + part * 8] = src[idx];
    }

    for (int idx = tid; idx < 32 * 128; idx += 128) {
        const int v = idx & 31, k = idx >> 5;
        const float val = (v < VV) ? dense_W[k * VV + v] : 0.0f;
        w_s[v * 136 + k] = __float2half_rn(val);
    }
    if (tid < 32) bias_s[tid] = (tid < VV) ? dense_b[tid] : 0.0f;
    __syncthreads();

    const int gi = lane >> 2;
    const int ci = lane & 3;
    const int m0 = wid * 16;

    float c[4][4] = {};
    #pragma unroll
    for (int ks = 0; ks < 8; ks++) {
        const int k = ks * 16 + ci * 2;
        const u32 a0 = *(const u32*)&hs[(m0 + gi)     * 136 + k];
        const u32 a1 = *(const u32*)&hs[(m0 + gi + 8) * 136 + k];
        const u32 a2 = *(const u32*)&hs[(m0 + gi)     * 136 + k + 8];
        const u32 a3 = *(const u32*)&hs[(m0 + gi + 8) * 136 + k + 8];
        #pragma unroll
        for (int nt = 0; nt < 4; nt++) {
            const int cc = nt * 8 + gi;
            const u32 b0 = *(const u32*)&w_s[cc * 136 + k];
            const u32 b1 = *(const u32*)&w_s[cc * 136 + k + 8];
            asm volatile(
                "mma.sync.aligned.m16n8k16.row.col.f32.f16.f16.f32 "
                "{%0,%1,%2,%3}, {%4,%5,%6,%7}, {%8,%9}, {%0,%1,%2,%3};"
                : "+f"(c[nt][0]), "+f"(c[nt][1]), "+f"(c[nt][2]), "+f"(c[nt][3])
                : "r"(a0), "r"(a1), "r"(a2), "r"(a3), "r"(b0), "r"(b1));
        }
    }

    // hs dead from here; Ls takes over the storage
    __syncthreads();

    #pragma unroll
    for (int nt = 0; nt < 4; nt++) {
        const int col = nt * 8 + ci * 2;
        const int r0 = m0 + gi;
        if (col < VV) {
            Ls[r0 * VV + col]       = c[nt][0] + bias_s[col];
            Ls[(r0 + 8) * VV + col] = c[nt][2] + bias_s[col];
        }
        if (col + 1 < VV) {
            Ls[r0 * VV + col + 1]       = c[nt][1] + bias_s[col + 1];
            Ls[(r0 + 8) * VV + col + 1] = c[nt][3] + bias_s[col + 1];
        }
    }
    __syncthreads();

    float4* dst = (float4*)(out + tok0 * VV);
    const float4* srcL = (const float4*)Ls;
    #pragma unroll
    for (int i = 0; i < 4; i++) {
        const int idx = tid + 128 * i;
        if (idx < (64 * VV) / 4) dst[idx] = srcL[idx];
    }
}

// =====================================================================
extern "C" void kernel_launch(void* const* d_in, const int* in_sizes, int n_in,
                              void* d_out, int out_size) {
    const int*   enc_ids = (const int*)  d_in[0];
    const int*   dec_ids = (const int*)  d_in[1];
    const float* embed   = (const float*)d_in[2];
    const float* enc_Wx  = (const float*)d_in[3];
    const float* enc_Wh  = (const float*)d_in[4];
    const float* enc_b   = (const float*)d_in[5];
    const float* dec_Wx  = (const float*)d_in[6];
    const float* dec_Wh  = (const float*)d_in[7];
    const float* dec_b   = (const float*)d_in[8];
    const float* dense_W = (const float*)d_in[9];
    const float* dense_b = (const float*)d_in[10];
    float* out = (float*)d_out;

    scan_kernel<<<BB / 2, 256>>>(enc_ids, dec_ids, embed,
                                 enc_Wx, enc_Wh, enc_b,
                                 dec_Wx, dec_Wh, dec_b);
    logits_kernel<<<(BB * SD) / 64, 128>>>(dense_W, dense_b, out);
}

// round 15
// speedup vs baseline: 1.9240x; 1.9240x over previous
#include <cuda_runtime.h>
#include <cuda_fp16.h>
#include <cstdint>
#include <math.h>

// Problem constants
#define VV 27
#define EE 64
#define HH 128
#define BB 256
#define SE 512
#define SD 512

typedef unsigned long long ull;
typedef unsigned int u32;

// Scratch for decoder hidden states, fp16: [B, S_DEC, H] = 32 MB.
__device__ __half g_dec_h[(size_t)BB * SD * HH];

// ---- packed fp32x2 helpers (sm_103a FFMA2 / FADD2) ----
__device__ __forceinline__ void ffma2(ull& d, ull a, ull b) {
    asm("fma.rn.f32x2 %0, %1, %2, %0;" : "+l"(d) : "l"(a), "l"(b));
}
__device__ __forceinline__ ull addp2(ull a, ull b) {
    ull r; asm("add.rn.f32x2 %0, %1, %2;" : "=l"(r) : "l"(a), "l"(b)); return r;
}
__device__ __forceinline__ ull pack2(float x, float y) {
    ull r; asm("mov.b64 %0, {%1, %2};" : "=l"(r) : "f"(x), "f"(y)); return r;
}
__device__ __forceinline__ float2 unpack2(ull v) {
    float2 r; asm("mov.b64 {%0, %1}, %2;" : "=f"(r.x), "=f"(r.y) : "l"(v)); return r;
}

// Fast-but-accurate tanh: 1 - 2/(exp(2x)+1). abs err ~1e-6.
__device__ __forceinline__ float fast_tanh(float x) {
    float e = __expf(x * 2.0f);
    return 1.0f - __fdividef(2.0f, e + 1.0f);
}

// =====================================================================
// Kernel 1: fused encoder+decoder scan (R12, best measured: ~327us).
// 128 CTAs x 256 threads; grp = tid>>7 = row, j = tid&127 = unit.
// Cross-group ring: bar.sync (gate + intra-group sync) -> intact
// unrolled dot -> bar.arrive pinned on the RAW accumulators ->
// reduce/tanh/STS in the partner-hidden window.
// =====================================================================
__global__ void __launch_bounds__(256, 1) scan_kernel(
    const int*   __restrict__ enc_ids, const int* __restrict__ dec_ids,
    const float* __restrict__ embed,
    const float* __restrict__ enc_Wx, const float* __restrict__ enc_Wh,
    const float* __restrict__ enc_b,
    const float* __restrict__ dec_Wx, const float* __restrict__ dec_Wh,
    const float* __restrict__ dec_b)
{
    __shared__ float tabE[VV][HH];
    __shared__ float tabD[VV][HH];
    __shared__ float emb_s[VV * EE];
    __shared__ __align__(16) float hbuf[2][2][HH];
    __shared__ int   idsE[2][SE];
    __shared__ int   idsD[2][SD];

    const int tid  = threadIdx.x;
    const int grp  = tid >> 7;
    const int j    = tid & (HH - 1);
    const int row0 = blockIdx.x * 2;
    const int row  = row0 + grp;

    for (int i = tid; i < VV * EE; i += 256) emb_s[i] = embed[i];
    for (int i = tid; i < SE; i += 256) {
        idsE[0][i] = enc_ids[(size_t)row0 * SE + i];
        idsE[1][i] = enc_ids[(size_t)(row0 + 1) * SE + i];
    }
    for (int i = tid; i < SD; i += 256) {
        idsD[0][i] = dec_ids[(size_t)row0 * SD + i];
        idsD[1][i] = dec_ids[(size_t)(row0 + 1) * SD + i];
    }
    __syncthreads();

    for (int idx = tid; idx < VV * HH; idx += 256) {
        const int v = idx / HH;
        const int h = idx - v * HH;
        float sE = enc_b[h];
        float sD = dec_b[h];
        #pragma unroll 8
        for (int e = 0; e < EE; e++) {
            const float em = emb_s[v * EE + e];
            sE = fmaf(em, enc_Wx[e * HH + h], sE);
            sD = fmaf(em, dec_Wx[e * HH + h], sD);
        }
        tabE[v][h] = sE;
        tabD[v][h] = sD;
    }

    if (grp == 0) { hbuf[0][0][j] = 0.0f; hbuf[0][1][j] = 0.0f; }
    __syncthreads();

    ull w2[HH / 2];
    #pragma unroll
    for (int k = 0; k < HH / 2; k++)
        w2[k] = pack2(enc_Wh[(2 * k) * HH + j], enc_Wh[(2 * k + 1) * HH + j]);

    // prime the ring
    if (grp == 1)
        asm volatile("bar.arrive 4, 256;" ::: "memory");

    // ---- encoder phase ----
    int cur = 0;
    float tb = tabE[idsE[grp][0]][j];
    for (int t = 0; t < SE; t++) {
        if (grp == 0) asm volatile("bar.sync 4, 256;" ::: "memory");
        else          asm volatile("bar.sync 3, 256;" ::: "memory");

        const ulonglong2* hq = (const ulonglong2*)hbuf[cur][grp];
        ull a0 = pack2(tb, 0.0f), a1 = 0, a2 = 0, a3 = 0;
        #pragma unroll
        for (int q = 0; q < HH / 4; q += 2) {
            ulonglong2 h0 = hq[q];
            ulonglong2 h1 = hq[q + 1];
            ffma2(a0, h0.x, w2[2 * q + 0]);
            ffma2(a1, h0.y, w2[2 * q + 1]);
            ffma2(a2, h1.x, w2[2 * q + 2]);
            ffma2(a3, h1.y, w2[2 * q + 3]);
        }
        if (grp == 0) asm volatile("bar.arrive 3, 256;"
                                   :: "l"(a0), "l"(a1), "l"(a2), "l"(a3));
        else          asm volatile("bar.arrive 4, 256;"
                                   :: "l"(a0), "l"(a1), "l"(a2), "l"(a3));

        const int tn = (t + 1 < SE) ? t + 1 : t;
        const float nb = tabE[idsE[grp][tn]][j];

        float2 s = unpack2(addp2(addp2(a0, a2), addp2(a1, a3)));
        const float hn = fast_tanh(s.x + s.y);
        hbuf[cur ^ 1][grp][j] = hn;
        cur ^= 1;
        tb = nb;
    }

    // ---- decoder phase ----
    #pragma unroll
    for (int k = 0; k < HH / 2; k++)
        w2[k] = pack2(dec_Wh[(2 * k) * HH + j], dec_Wh[(2 * k + 1) * HH + j]);

    __half* outrow = g_dec_h + (size_t)row * SD * HH;
    tb = tabD[idsD[grp][0]][j];
    for (int t = 0; t < SD; t++) {
        if (grp == 0) asm volatile("bar.sync 4, 256;" ::: "memory");
        else          asm volatile("bar.sync 3, 256;" ::: "memory");

        const ulonglong2* hq = (const ulonglong2*)hbuf[cur][grp];
        ull a0 = pack2(tb, 0.0f), a1 = 0, a2 = 0, a3 = 0;
        #pragma unroll
        for (int q = 0; q < HH / 4; q += 2) {
            ulonglong2 h0 = hq[q];
            ulonglong2 h1 = hq[q + 1];
            ffma2(a0, h0.x, w2[2 * q + 0]);
            ffma2(a1, h0.y, w2[2 * q + 1]);
            ffma2(a2, h1.x, w2[2 * q + 2]);
            ffma2(a3, h1.y, w2[2 * q + 3]);
        }
        if (grp == 0) asm volatile("bar.arrive 3, 256;"
                                   :: "l"(a0), "l"(a1), "l"(a2), "l"(a3));
        else          asm volatile("bar.arrive 4, 256;"
                                   :: "l"(a0), "l"(a1), "l"(a2), "l"(a3));

        const int tn = (t + 1 < SD) ? t + 1 : t;
        const float nb = tabD[idsD[grp][tn]][j];

        float2 s = unpack2(addp2(addp2(a0, a2), addp2(a1, a3)));
        const float hn = fast_tanh(s.x + s.y);
        hbuf[cur ^ 1][grp][j] = hn;
        outrow[t * HH + j] = __float2half_rn(hn);   // off-chain store
        cur ^= 1;
        tb = nb;
    }
}

// =====================================================================
// Kernel 2: logits via tensor cores (R12 structure: 64-token tiles,
// 2048 CTAs x 128 threads, separate Ls, NO reg cap). Single change vs
// R12: dense_W staged with 7 vectorized LDG.128 of contiguous rows +
// scattered STS.16 (issue-only), replacing 32 serial strided LDG.32
// gathers. Pad rows v in [27,32) zeroed as 85 uint4 — disjoint from
// the live fill, so no extra sync needed.
// =====================================================================
__global__ void __launch_bounds__(128) logits_kernel(
    const float* __restrict__ dense_W, const float* __restrict__ dense_b,
    float* __restrict__ out)
{
    __shared__ __align__(16) __half hs[64 * 136];    // 17 KB h tile
    __shared__ __align__(16) __half w_s[32 * 136];   // 8.5 KB W^T
    __shared__ __align__(16) float  Ls[64 * VV];     // 6.9 KB logit tile
    __shared__ float bias_s[32];

    const int tid  = threadIdx.x;
    const int lane = tid & 31;
    const int wid  = tid >> 5;            // 0..3
    const size_t tok0 = (size_t)blockIdx.x * 64;

    // stage h tile: 1024 uint4, 8 per thread
    const uint4* src = (const uint4*)(g_dec_h + tok0 * HH);
    #pragma unroll
    for (int i = 0; i < 8; i++) {
        const int idx = tid + 128 * i;
        const int row = idx >> 4, part = idx & 15;
        *(uint4*)&hs[row * 136 + part * 8] = src[idx];
    }

    // zero ONLY pad rows v in [27,32): 5*136 halfs = 85 uint4
    if (tid < 85)
        ((uint4*)(w_s + 27 * 136))[tid] = make_uint4(0, 0, 0, 0);

    // vectorized W fill: dense_W = [128][27] f32 row-major = 864 float4.
    // float index f = k*27 + v  ->  w_s[v*136+k] (pads untouched: v<27)
    for (int i = tid; i < 864; i += 128) {
        const float4 wv = ((const float4*)dense_W)[i];
        int f = i * 4;
        int k = f / 27;
        int v = f - k * 27;
        w_s[v * 136 + k] = __float2half_rn(wv.x);
        if (++v == VV) { v = 0; k++; }
        w_s[v * 136 + k] = __float2half_rn(wv.y);
        if (++v == VV) { v = 0; k++; }
        w_s[v * 136 + k] = __float2half_rn(wv.z);
        if (++v == VV) { v = 0; k++; }
        w_s[v * 136 + k] = __float2half_rn(wv.w);
    }
    if (tid < 32) bias_s[tid] = (tid < VV) ? dense_b[tid] : 0.0f;
    __syncthreads();

    const int gi = lane >> 2;
    const int ci = lane & 3;
    const int m0 = wid * 16;

    float c[4][4] = {};
    #pragma unroll
    for (int ks = 0; ks < 8; ks++) {
        const int k = ks * 16 + ci * 2;
        const u32 a0 = *(const u32*)&hs[(m0 + gi)     * 136 + k];
        const u32 a1 = *(const u32*)&hs[(m0 + gi + 8) * 136 + k];
        const u32 a2 = *(const u32*)&hs[(m0 + gi)     * 136 + k + 8];
        const u32 a3 = *(const u32*)&hs[(m0 + gi + 8) * 136 + k + 8];
        #pragma unroll
        for (int nt = 0; nt < 4; nt++) {
            const int cc = nt * 8 + gi;
            const u32 b0 = *(const u32*)&w_s[cc * 136 + k];
            const u32 b1 = *(const u32*)&w_s[cc * 136 + k + 8];
            asm volatile(
                "mma.sync.aligned.m16n8k16.row.col.f32.f16.f16.f32 "
                "{%0,%1,%2,%3}, {%4,%5,%6,%7}, {%8,%9}, {%0,%1,%2,%3};"
                : "+f"(c[nt][0]), "+f"(c[nt][1]), "+f"(c[nt][2]), "+f"(c[nt][3])
                : "r"(a0), "r"(a1), "r"(a2), "r"(a3), "r"(b0), "r"(b1));
        }
    }

    #pragma unroll
    for (int nt = 0; nt < 4; nt++) {
        const int col = nt * 8 + ci * 2;
        const int r0 = m0 + gi;
        if (col < VV) {
            Ls[r0 * VV + col]       = c[nt][0] + bias_s[col];
            Ls[(r0 + 8) * VV + col] = c[nt][2] + bias_s[col];
        }
        if (col + 1 < VV) {
            Ls[r0 * VV + col + 1]       = c[nt][1] + bias_s[col + 1];
            Ls[(r0 + 8) * VV + col + 1] = c[nt][3] + bias_s[col + 1];
        }
    }
    __syncthreads();

    float4* dst = (float4*)(out + tok0 * VV);
    const float4* srcL = (const float4*)Ls;
    #pragma unroll
    for (int i = 0; i < 4; i++) {
        const int idx = tid + 128 * i;
        if (idx < (64 * VV) / 4) dst[idx] = srcL[idx];
    }
}

// =====================================================================
extern "C" void kernel_launch(void* const* d_in, const int* in_sizes, int n_in,
                              void* d_out, int out_size) {
    const int*   enc_ids = (const int*)  d_in[0];
    const int*   dec_ids = (const int*)  d_in[1];
    const float* embed   = (const float*)d_in[2];
    const float* enc_Wx  = (const float*)d_in[3];
    const float* enc_Wh  = (const float*)d_in[4];
    const float* enc_b   = (const float*)d_in[5];
    const float* dec_Wx  = (const float*)d_in[6];
    const float* dec_Wh  = (const float*)d_in[7];
    const float* dec_b   = (const float*)d_in[8];
    const float* dense_W = (const float*)d_in[9];
    const float* dense_b = (const float*)d_in[10];
    float* out = (float*)d_out;

    scan_kernel<<<BB / 2, 256>>>(enc_ids, dec_ids, embed,
                                 enc_Wx, enc_Wh, enc_b,
                                 dec_Wx, dec_Wh, dec_b);
    logits_kernel<<<(BB * SD) / 64, 128>>>(dense_W, dense_b, out);
}